// round 8
// baseline (speedup 1.0000x reference)
#include <cuda_runtime.h>
#include <math.h>

#define NEG_K 32
#define TEMP 0.07f
#define INV_T (1.0f / 0.07f)

// Self-resetting cross-block accumulator (zero-initialized; last block resets).
__device__ float g_sum;
__device__ int   g_count;

__global__ __launch_bounds__(512) void infonce_kernel(
    const float* __restrict__ hs,       // [B, S, H]
    const int*   __restrict__ selection,// [B]
    const int*   __restrict__ mask,     // [B, S]
    const float* __restrict__ noise,    // [loss_size, NEG_K]
    float* __restrict__ out,            // [1]
    int B, int S, int H, int valid)
{
    const int l    = blockIdx.x;        // grid = loss_size
    const int tid  = threadIdx.x;
    const int lane = tid & 31;
    const int warp = tid >> 5;          // 0..15

    __shared__ float logits_s[NEG_K + 1];

    const int sel = __ldg(selection + l);   // uniform, issues first

    // Stream map: warp0 -> j=0(positive),1,2 ; warp w>=1 -> j=2w+1, 2w+2. Covers 0..32.
    const int jbase = (warp == 0) ? 0 : (2 * warp + 1);
    const int cnt   = (warp == 0) ? 3 : 2;

    const int H4 = H >> 2;
    const float4* __restrict__ a4 = (const float4*)(hs + ((size_t)l * S + sel) * H);

    // Noise loads for this warp's negatives (lanes 0..cnt-1)
    float nz = 0.0f;
    {
        int nj = jbase + lane;
        if (lane < cnt && nj >= 1)
            nz = __ldg(noise + (size_t)l * NEG_K + (nj - 1));
    }

    // Per-warp mask sum (independent of sel/anchor -> overlaps with anchor loads)
    int msum = 0;
    {
        const int* mrow = mask + (size_t)l * S;
        #pragma unroll 8
        for (int s = lane; s < S; s += 32) msum += mrow[s];
        #pragma unroll
        for (int o = 16; o; o >>= 1) msum += __shfl_xor_sync(0xffffffffu, msum, o);
    }
    const int len_l = msum;
    const bool sir = (sel >= 1) && (sel <= len_l - 1);
    const int n_valid = sir ? (len_l - 2) : (len_l - 1);

    // Build 3 stream pointers (unused -> alias anchor, L1 hits, result discarded)
    const float4* bp[3];
    #pragma unroll
    for (int s = 0; s < 3; s++) {
        const int j = jbase + s;
        const float4* p;
        if (s >= cnt || j > NEG_K) {
            p = a4;
        } else if (j == 0) {
            p = (const float4*)(hs + ((size_t)(valid + l) * S + sel) * H);  // positive
        } else {
            float nzs = __shfl_sync(0xffffffffu, nz, s);
            int cand = (int)floorf(nzs * (float)n_valid) + 1;
            if (sir && cand >= sel) cand += 1;
            p = (const float4*)(hs + ((size_t)l * S + cand) * H);
        }
        bp[s] = p;
    }

    float acc0 = 0.f, acc1 = 0.f, acc2 = 0.f;
    if (H4 == 192) {
        // Fast path: exactly 6 iterations, fully unrolled -> one front load batch
        #pragma unroll
        for (int i = 0; i < 6; i++) {
            const int idx = lane + 32 * i;
            float4 a  = a4[idx];
            float4 b0 = bp[0][idx];
            float4 b1 = bp[1][idx];
            float4 b2 = bp[2][idx];
            acc0 += a.x*b0.x + a.y*b0.y + a.z*b0.z + a.w*b0.w;
            acc1 += a.x*b1.x + a.y*b1.y + a.z*b1.z + a.w*b1.w;
            acc2 += a.x*b2.x + a.y*b2.y + a.z*b2.z + a.w*b2.w;
        }
    } else {
        for (int i = lane; i < H4; i += 32) {
            float4 a  = a4[i];
            float4 b0 = bp[0][i];
            float4 b1 = bp[1][i];
            float4 b2 = bp[2][i];
            acc0 += a.x*b0.x + a.y*b0.y + a.z*b0.z + a.w*b0.w;
            acc1 += a.x*b1.x + a.y*b1.y + a.z*b1.z + a.w*b1.w;
            acc2 += a.x*b2.x + a.y*b2.y + a.z*b2.z + a.w*b2.w;
        }
    }
    #pragma unroll
    for (int o = 16; o; o >>= 1) {
        acc0 += __shfl_xor_sync(0xffffffffu, acc0, o);
        acc1 += __shfl_xor_sync(0xffffffffu, acc1, o);
        acc2 += __shfl_xor_sync(0xffffffffu, acc2, o);
    }
    if (lane == 0) {
        logits_s[jbase] = acc0;
        logits_s[jbase + 1] = acc1;
        if (cnt == 3) logits_s[jbase + 2] = acc2;
    }
    __syncthreads();

    // Warp 0: parallel logsumexp over 33 logits
    if (warp == 0) {
        float v = logits_s[lane] * INV_T;
        float e = logits_s[NEG_K] * INV_T;     // element 32, folded at lane 0
        float m = (lane == 0) ? fmaxf(v, e) : v;
        #pragma unroll
        for (int o = 16; o; o >>= 1) m = fmaxf(m, __shfl_xor_sync(0xffffffffu, m, o));
        float sse = __expf(v - m);
        if (lane == 0) sse += __expf(e - m);
        #pragma unroll
        for (int o = 16; o; o >>= 1) sse += __shfl_xor_sync(0xffffffffu, sse, o);

        if (lane == 0) {
            float rowloss = (m + logf(sse)) - logits_s[0] * INV_T;
            atomicAdd(&g_sum, rowloss);
            __threadfence();
            int done = atomicAdd(&g_count, 1);
            if (done == gridDim.x - 1) {
                float total = atomicExch(&g_sum, 0.0f);   // reset for graph replay
                g_count = 0;
                out[0] = (total + (float)valid * logf((float)(NEG_K + 1))) / (float)B;
            }
        }
    }
}

extern "C" void kernel_launch(void* const* d_in, const int* in_sizes, int n_in,
                              void* d_out, int out_size) {
    const float* hs        = (const float*)d_in[0]; // [B,S,H]
    const int*   selection = (const int*)  d_in[1]; // [B]
    const int*   mask      = (const int*)  d_in[2]; // [B,S]
    const float* noise     = (const float*)d_in[3]; // [loss_size, NEG_K]
    float*       out       = (float*)d_out;

    const int B = in_sizes[1];
    const int S = in_sizes[2] / B;
    const int H = in_sizes[0] / (B * S);
    const int loss_size = in_sizes[3] / NEG_K;      // from noise shape (host-side)
    const int valid = B - loss_size;

    infonce_kernel<<<loss_size, 512>>>(hs, selection, mask, noise, out, B, S, H, valid);
}

// round 11
// speedup vs baseline: 1.0173x; 1.0173x over previous
#include <cuda_runtime.h>
#include <math.h>

#define NEG_K 32
#define TEMP 0.07f
#define INV_T (1.0f / 0.07f)
#define MAX_B 1024

// Global scratch + self-resetting counters (zero-initialized at load;
// every counter is returned to 0 before the launch ends -> graph-replay safe).
__device__ float g_logits[MAX_B * (NEG_K + 1)];
__device__ int   g_rowcnt[MAX_B];
__device__ float g_sum;
__device__ int   g_count;

__global__ __launch_bounds__(128) void infonce_kernel(
    const float* __restrict__ hs,       // [B, S, H]
    const int*   __restrict__ selection,// [B]
    const int*   __restrict__ mask,     // [B, S]
    const float* __restrict__ noise,    // [loss_size, NEG_K]
    float* __restrict__ out,            // [1]
    int B, int S, int H, int valid, int loss_size)
{
    const int bid  = blockIdx.x;        // grid = 4 * loss_size
    const int l    = bid >> 2;
    const int q    = bid & 3;
    const int lane = threadIdx.x & 31;
    const int warp = threadIdx.x >> 5;  // 0..3

    const int sel = __ldg(selection + l);           // independent load 1

    // Warp's negatives: j = 8q + 2w + 1, 8q + 2w + 2  (covers 1..32)
    const int jbase  = q * 8 + warp * 2 + 1;
    const bool haspos = (q == 0) && (warp == 0);    // also owns j=0

    // independent load 2: this warp's two noise values
    float nz = 0.0f;
    if (lane < 2) nz = __ldg(noise + (size_t)l * NEG_K + (jbase - 1 + lane));

    // independent load 3: mask row sum (8 ints/lane, coalesced)
    int msum = 0;
    {
        const int* mrow = mask + (size_t)l * S;
        #pragma unroll 8
        for (int s = lane; s < S; s += 32) msum += mrow[s];
        #pragma unroll
        for (int o = 16; o; o >>= 1) msum += __shfl_xor_sync(0xffffffffu, msum, o);
    }
    const int len_l = msum;
    const bool sir = (sel >= 1) && (sel <= len_l - 1);
    const int n_valid = sir ? (len_l - 2) : (len_l - 1);

    const int H4 = H >> 2;
    const float4* __restrict__ a4 = (const float4*)(hs + ((size_t)l * S + sel) * H);

    // Two negative stream pointers
    const float4* bp[2];
    #pragma unroll
    for (int s = 0; s < 2; s++) {
        float nzs = __shfl_sync(0xffffffffu, nz, s);
        int cand = (int)floorf(nzs * (float)n_valid) + 1;
        if (sir && cand >= sel) cand += 1;
        bp[s] = (const float4*)(hs + ((size_t)l * S + cand) * H);
    }

    float acc0 = 0.f, acc1 = 0.f, accp = 0.f;
    if (haspos) {
        const float4* pp = (const float4*)(hs + ((size_t)(valid + l) * S + sel) * H);
        if (H4 == 192) {
            #pragma unroll
            for (int i = 0; i < 6; i++) {
                const int idx = lane + 32 * i;
                float4 a  = a4[idx];
                float4 b0 = bp[0][idx];
                float4 b1 = bp[1][idx];
                float4 bp2 = pp[idx];
                acc0 += a.x*b0.x + a.y*b0.y + a.z*b0.z + a.w*b0.w;
                acc1 += a.x*b1.x + a.y*b1.y + a.z*b1.z + a.w*b1.w;
                accp += a.x*bp2.x + a.y*bp2.y + a.z*bp2.z + a.w*bp2.w;
            }
        } else {
            for (int i = lane; i < H4; i += 32) {
                float4 a  = a4[i];
                float4 b0 = bp[0][i];
                float4 b1 = bp[1][i];
                float4 bp2 = pp[i];
                acc0 += a.x*b0.x + a.y*b0.y + a.z*b0.z + a.w*b0.w;
                acc1 += a.x*b1.x + a.y*b1.y + a.z*b1.z + a.w*b1.w;
                accp += a.x*bp2.x + a.y*bp2.y + a.z*bp2.z + a.w*bp2.w;
            }
        }
    } else {
        if (H4 == 192) {
            #pragma unroll
            for (int i = 0; i < 6; i++) {
                const int idx = lane + 32 * i;
                float4 a  = a4[idx];
                float4 b0 = bp[0][idx];
                float4 b1 = bp[1][idx];
                acc0 += a.x*b0.x + a.y*b0.y + a.z*b0.z + a.w*b0.w;
                acc1 += a.x*b1.x + a.y*b1.y + a.z*b1.z + a.w*b1.w;
            }
        } else {
            for (int i = lane; i < H4; i += 32) {
                float4 a  = a4[i];
                float4 b0 = bp[0][i];
                float4 b1 = bp[1][i];
                acc0 += a.x*b0.x + a.y*b0.y + a.z*b0.z + a.w*b0.w;
                acc1 += a.x*b1.x + a.y*b1.y + a.z*b1.z + a.w*b1.w;
            }
        }
    }
    #pragma unroll
    for (int o = 16; o; o >>= 1) {
        acc0 += __shfl_xor_sync(0xffffffffu, acc0, o);
        acc1 += __shfl_xor_sync(0xffffffffu, acc1, o);
        accp += __shfl_xor_sync(0xffffffffu, accp, o);
    }
    if (lane == 0) {
        float* lrow = g_logits + (size_t)l * (NEG_K + 1);
        lrow[jbase]     = acc0;
        lrow[jbase + 1] = acc1;
        if (haspos) lrow[0] = accp;
    }
    __syncthreads();

    // One thread per CTA: per-row completion; 4th finisher does the LSE.
    if (threadIdx.x == 0) {
        __threadfence();
        int old = atomicAdd(&g_rowcnt[l], 1);
        if (old == 3) {
            g_rowcnt[l] = 0;            // self-reset (all 4 increments done)
            __threadfence();            // acquire: logits of other CTAs visible
            const float* lrow = g_logits + (size_t)l * (NEG_K + 1);
            float v[NEG_K + 1];
            #pragma unroll
            for (int j = 0; j <= NEG_K; j++) v[j] = lrow[j] * INV_T;
            float m = v[0];
            #pragma unroll
            for (int j = 1; j <= NEG_K; j++) m = fmaxf(m, v[j]);
            float sse = 0.0f;
            #pragma unroll
            for (int j = 0; j <= NEG_K; j++) sse += __expf(v[j] - m);
            float rowloss = (m + logf(sse)) - v[0];

            atomicAdd(&g_sum, rowloss);
            __threadfence();
            int done = atomicAdd(&g_count, 1);
            if (done == loss_size - 1) {
                float total = atomicExch(&g_sum, 0.0f);   // reset for replay
                g_count = 0;
                out[0] = (total + (float)valid * logf((float)(NEG_K + 1))) / (float)B;
            }
        }
    }
}

extern "C" void kernel_launch(void* const* d_in, const int* in_sizes, int n_in,
                              void* d_out, int out_size) {
    const float* hs        = (const float*)d_in[0]; // [B,S,H]
    const int*   selection = (const int*)  d_in[1]; // [B]
    const int*   mask      = (const int*)  d_in[2]; // [B,S]
    const float* noise     = (const float*)d_in[3]; // [loss_size, NEG_K]
    float*       out       = (float*)d_out;

    const int B = in_sizes[1];
    const int S = in_sizes[2] / B;
    const int H = in_sizes[0] / (B * S);
    const int loss_size = in_sizes[3] / NEG_K;      // from noise shape (host-side)
    const int valid = B - loss_size;

    infonce_kernel<<<loss_size * 4, 128>>>(hs, selection, mask, noise, out,
                                           B, S, H, valid, loss_size);
}

// round 12
// speedup vs baseline: 1.0753x; 1.0571x over previous
#include <cuda_runtime.h>
#include <math.h>
#include <stdint.h>

#define NEG_K 32
#define TEMP 0.07f
#define INV_T (1.0f / 0.07f)

#define H_FIX 768
#define H4_FIX 192
#define GSTREAMS 6           // streams per group
#define NGROUPS 6            // ceil(33/6)
#define ROW_BYTES (H_FIX * 4)   // 3072

// Self-resetting cross-block accumulator (zero-initialized; reset each launch).
__device__ float g_sum;
__device__ int   g_count;

__device__ __forceinline__ uint32_t smem_u32(const void* p) {
    return (uint32_t)__cvta_generic_to_shared(p);
}
__device__ __forceinline__ void mbar_init(uint32_t addr, uint32_t cnt) {
    asm volatile("mbarrier.init.shared::cta.b64 [%0], %1;" :: "r"(addr), "r"(cnt) : "memory");
}
__device__ __forceinline__ void mbar_expect_tx(uint32_t addr, uint32_t bytes) {
    asm volatile("mbarrier.arrive.expect_tx.shared::cta.b64 _, [%0], %1;"
                 :: "r"(addr), "r"(bytes) : "memory");
}
__device__ __forceinline__ void bulk_cp(uint32_t dst, const void* src, uint32_t bytes, uint32_t mbar) {
    asm volatile("cp.async.bulk.shared::cta.global.mbarrier::complete_tx::bytes [%0], [%1], %2, [%3];"
                 :: "r"(dst), "l"(src), "r"(bytes), "r"(mbar) : "memory");
}
__device__ __forceinline__ void mbar_wait(uint32_t addr, uint32_t parity) {
    asm volatile(
        "{\n\t.reg .pred P;\n"
        "W_%=:\n\t"
        "mbarrier.try_wait.parity.acquire.cta.shared::cta.b64 P, [%0], %1, 0x989680;\n\t"
        "@P bra D_%=;\n\t"
        "bra W_%=;\n"
        "D_%=:\n\t}"
        :: "r"(addr), "r"(parity) : "memory");
}

// ---------------- bulk-pipeline kernel (H == 768) ----------------
__global__ __launch_bounds__(192) void infonce_bulk_kernel(
    const float* __restrict__ hs,       // [B, S, H]
    const int*   __restrict__ selection,// [B]
    const int*   __restrict__ mask,     // [B, S]
    const float* __restrict__ noise,    // [loss_size, NEG_K]
    float* __restrict__ out,            // [1]
    int B, int S, int valid, int loss_size)
{
    const int l    = blockIdx.x;
    const int tid  = threadIdx.x;
    const int lane = tid & 31;
    const int warp = tid >> 5;          // 0..5

    __shared__ __align__(128) float anchor_s[H_FIX];
    __shared__ __align__(128) float ring[2][GSTREAMS * H_FIX];
    __shared__ float logits_s[NEG_K + 1];
    __shared__ int   cand_s[NEG_K];
    __shared__ __align__(8) unsigned long long mbar_store[2];

    const uint32_t mb0 = smem_u32(&mbar_store[0]);
    const uint32_t mb1 = smem_u32(&mbar_store[1]);

    const int sel = __ldg(selection + l);   // uniform, issues immediately

    if (tid == 32) { mbar_init(mb0, 1); mbar_init(mb1, 1); }

    // warp 0: noise + mask-sum + candidate indices (one parallel trip)
    if (warp == 0) {
        float nz = __ldg(noise + (size_t)l * NEG_K + lane);
        int msum = 0;
        const int* mrow = mask + (size_t)l * S;
        for (int s = lane; s < S; s += 32) msum += mrow[s];
        #pragma unroll
        for (int o = 16; o; o >>= 1) msum += __shfl_xor_sync(0xffffffffu, msum, o);
        const int len_l = msum;
        const bool sir = (sel >= 1) && (sel <= len_l - 1);
        const int n_valid = sir ? (len_l - 2) : (len_l - 1);
        int cand = (int)floorf(nz * (float)n_valid) + 1;
        if (sir && cand >= sel) cand += 1;
        cand_s[lane] = cand;
    }
    __syncthreads();   // cand_s + mbar init visible

    // Issue groups 0 and 1 (and anchor) into the ring.
    // group g covers streams j = g*GSTREAMS + s, s<GSTREAMS, j<=32.
    // j==0 -> positive row (valid+l, sel); j>=1 -> negative cand_s[j-1].
    if (tid == 0) {
        mbar_expect_tx(mb0, GSTREAMS * ROW_BYTES + ROW_BYTES);  // g0 + anchor
        mbar_expect_tx(mb1, GSTREAMS * ROW_BYTES);              // g1
        bulk_cp(smem_u32(anchor_s),
                hs + ((size_t)l * S + sel) * H_FIX, ROW_BYTES, mb0);
    }
    if (tid < GSTREAMS) {  // group 0 streams
        const int j = tid;
        const float* src = (j == 0)
            ? hs + ((size_t)(valid + l) * S + sel) * H_FIX
            : hs + ((size_t)l * S + cand_s[j - 1]) * H_FIX;
        bulk_cp(smem_u32(&ring[0][tid * H_FIX]), src, ROW_BYTES, mb0);
    }
    if (tid >= 32 && tid < 32 + GSTREAMS) {  // group 1 streams
        const int s = tid - 32;
        const int j = GSTREAMS + s;
        const float* src = hs + ((size_t)l * S + cand_s[j - 1]) * H_FIX;
        bulk_cp(smem_u32(&ring[1][s * H_FIX]), src, ROW_BYTES, mb1);
    }

    // Pipeline: wait group g, compute, then refill slot with group g+2.
    const float4* a4s = (const float4*)anchor_s;
    #pragma unroll
    for (int g = 0; g < NGROUPS; g++) {
        const uint32_t mb = (g & 1) ? mb1 : mb0;
        mbar_wait(mb, (g >> 1) & 1);

        const int j = g * GSTREAMS + warp;
        if (j <= NEG_K) {
            const float4* v4 = (const float4*)&ring[g & 1][warp * H_FIX];
            float acc = 0.0f;
            #pragma unroll
            for (int i = 0; i < H4_FIX / 32; i++) {
                const int idx = lane + 32 * i;
                float4 a = a4s[idx];
                float4 b = v4[idx];
                acc += a.x*b.x + a.y*b.y + a.z*b.z + a.w*b.w;
            }
            #pragma unroll
            for (int o = 16; o; o >>= 1) acc += __shfl_xor_sync(0xffffffffu, acc, o);
            if (lane == 0) logits_s[j] = acc;
        }
        __syncthreads();   // slot fully consumed

        const int gn = g + 2;
        if (gn < NGROUPS) {
            const int base = gn * GSTREAMS;
            const int nstr = min(GSTREAMS, NEG_K + 1 - base);   // last group: 3
            const uint32_t mbn = (gn & 1) ? mb1 : mb0;
            if (tid == 0) mbar_expect_tx(mbn, (uint32_t)nstr * ROW_BYTES);
            if (tid < nstr) {
                const int j2 = base + tid;
                const float* src = hs + ((size_t)l * S + cand_s[j2 - 1]) * H_FIX;
                bulk_cp(smem_u32(&ring[gn & 1][tid * H_FIX]), src, ROW_BYTES, mbn);
            }
        }
    }

    // Warp 0: parallel logsumexp over 33 logits + grid reduction.
    if (warp == 0) {
        float v = logits_s[lane] * INV_T;
        float e = logits_s[NEG_K] * INV_T;
        float m = (lane == 0) ? fmaxf(v, e) : v;
        #pragma unroll
        for (int o = 16; o; o >>= 1) m = fmaxf(m, __shfl_xor_sync(0xffffffffu, m, o));
        float sse = __expf(v - m);
        if (lane == 0) sse += __expf(e - m);
        #pragma unroll
        for (int o = 16; o; o >>= 1) sse += __shfl_xor_sync(0xffffffffu, sse, o);

        if (lane == 0) {
            float rowloss = (m + logf(sse)) - logits_s[0] * INV_T;
            atomicAdd(&g_sum, rowloss);
            __threadfence();
            int done = atomicAdd(&g_count, 1);
            if (done == loss_size - 1) {
                float total = atomicExch(&g_sum, 0.0f);   // reset for graph replay
                g_count = 0;
                out[0] = (total + (float)valid * logf((float)(NEG_K + 1))) / (float)B;
            }
        }
    }
}

// ---------------- generic fallback (any H), LDG-based ----------------
__global__ __launch_bounds__(256) void infonce_generic_kernel(
    const float* __restrict__ hs, const int* __restrict__ selection,
    const int* __restrict__ mask, const float* __restrict__ noise,
    float* __restrict__ out, int B, int S, int H, int valid, int loss_size)
{
    const int l    = blockIdx.x;
    const int tid  = threadIdx.x;
    const int lane = tid & 31;
    const int warp = tid >> 5;

    __shared__ float logits_s[NEG_K + 1];
    __shared__ int   cand_s[NEG_K];
    __shared__ int   len_sh;

    const int sel = __ldg(selection + l);
    if (warp == 0) {
        float nz = __ldg(noise + (size_t)l * NEG_K + lane);
        int msum = 0;
        const int* mrow = mask + (size_t)l * S;
        for (int s = lane; s < S; s += 32) msum += mrow[s];
        #pragma unroll
        for (int o = 16; o; o >>= 1) msum += __shfl_xor_sync(0xffffffffu, msum, o);
        const int len_l = msum;
        const bool sir = (sel >= 1) && (sel <= len_l - 1);
        const int n_valid = sir ? (len_l - 2) : (len_l - 1);
        int cand = (int)floorf(nz * (float)n_valid) + 1;
        if (sir && cand >= sel) cand += 1;
        cand_s[lane] = cand;
        if (lane == 0) len_sh = len_l;
    }
    __syncthreads();

    const float* a = hs + ((size_t)l * S + sel) * H;
    for (int j = warp; j <= NEG_K; j += blockDim.x >> 5) {
        const float* v = (j == 0)
            ? hs + ((size_t)(valid + l) * S + sel) * H
            : hs + ((size_t)l * S + cand_s[j - 1]) * H;
        float acc = 0.0f;
        for (int i = lane; i < H; i += 32) acc += a[i] * v[i];
        #pragma unroll
        for (int o = 16; o; o >>= 1) acc += __shfl_xor_sync(0xffffffffu, acc, o);
        if (lane == 0) logits_s[j] = acc;
    }
    __syncthreads();

    if (tid == 0) {
        float m = -INFINITY;
        for (int j = 0; j <= NEG_K; j++) m = fmaxf(m, logits_s[j] * INV_T);
        float sse = 0.0f;
        for (int j = 0; j <= NEG_K; j++) sse += __expf(logits_s[j] * INV_T - m);
        float rowloss = (m + logf(sse)) - logits_s[0] * INV_T;
        atomicAdd(&g_sum, rowloss);
        __threadfence();
        int done = atomicAdd(&g_count, 1);
        if (done == loss_size - 1) {
            float total = atomicExch(&g_sum, 0.0f);
            g_count = 0;
            out[0] = (total + (float)valid * logf((float)(NEG_K + 1))) / (float)B;
        }
    }
}

extern "C" void kernel_launch(void* const* d_in, const int* in_sizes, int n_in,
                              void* d_out, int out_size) {
    const float* hs        = (const float*)d_in[0]; // [B,S,H]
    const int*   selection = (const int*)  d_in[1]; // [B]
    const int*   mask      = (const int*)  d_in[2]; // [B,S]
    const float* noise     = (const float*)d_in[3]; // [loss_size, NEG_K]
    float*       out       = (float*)d_out;

    const int B = in_sizes[1];
    const int S = in_sizes[2] / B;
    const int H = in_sizes[0] / (B * S);
    const int loss_size = in_sizes[3] / NEG_K;      // from noise shape (host-side)
    const int valid = B - loss_size;

    if (H == H_FIX) {
        infonce_bulk_kernel<<<loss_size, 192>>>(hs, selection, mask, noise, out,
                                                B, S, valid, loss_size);
    } else {
        infonce_generic_kernel<<<loss_size, 256>>>(hs, selection, mask, noise, out,
                                                   B, S, H, valid, loss_size);
    }
}

// round 13
// speedup vs baseline: 1.1805x; 1.0977x over previous
#include <cuda_runtime.h>
#include <math.h>
#include <stdint.h>

#define NEG_K 32
#define TEMP 0.07f
#define INV_T (1.0f / 0.07f)

#define H_FIX 768
#define GSTREAMS 6
#define NGROUPS 6            // 6*6=36 >= 33 streams (last group has 3)
#define RING 3
#define ROW_BYTES (H_FIX * 4)     // 3072
#define RING_BYTES (RING * GSTREAMS * H_FIX * 4)   // 55296

// Self-resetting cross-block accumulator (zero-initialized; reset each launch).
__device__ float g_sum;
__device__ int   g_count;

__device__ __forceinline__ uint32_t smem_u32(const void* p) {
    return (uint32_t)__cvta_generic_to_shared(p);
}
__device__ __forceinline__ void mbar_init(uint32_t addr, uint32_t cnt) {
    asm volatile("mbarrier.init.shared::cta.b64 [%0], %1;" :: "r"(addr), "r"(cnt) : "memory");
}
__device__ __forceinline__ void mbar_expect_tx(uint32_t addr, uint32_t bytes) {
    asm volatile("mbarrier.arrive.expect_tx.shared::cta.b64 _, [%0], %1;"
                 :: "r"(addr), "r"(bytes) : "memory");
}
__device__ __forceinline__ void bulk_cp(uint32_t dst, const void* src, uint32_t bytes, uint32_t mbar) {
    asm volatile("cp.async.bulk.shared::cta.global.mbarrier::complete_tx::bytes [%0], [%1], %2, [%3];"
                 :: "r"(dst), "l"(src), "r"(bytes), "r"(mbar) : "memory");
}
__device__ __forceinline__ void mbar_wait(uint32_t addr, uint32_t parity) {
    asm volatile(
        "{\n\t.reg .pred P;\n"
        "W_%=:\n\t"
        "mbarrier.try_wait.parity.acquire.cta.shared::cta.b64 P, [%0], %1, 0x989680;\n\t"
        "@P bra D_%=;\n\t"
        "bra W_%=;\n"
        "D_%=:\n\t}"
        :: "r"(addr), "r"(parity) : "memory");
}

// ---------------- bulk-pipeline kernel (H == 768) ----------------
__global__ __launch_bounds__(192, 4) void infonce_bulk_kernel(
    const float* __restrict__ hs,       // [B, S, H]
    const int*   __restrict__ selection,// [B]
    const int*   __restrict__ mask,     // [B, S]
    const float* __restrict__ noise,    // [loss_size, NEG_K]
    float* __restrict__ out,            // [1]
    int B, int S, int valid, int loss_size)
{
    extern __shared__ __align__(128) float ring[];   // [RING][GSTREAMS][H_FIX]

    const int l    = blockIdx.x;
    const int tid  = threadIdx.x;
    const int lane = tid & 31;
    const int warp = tid >> 5;          // 0..5

    __shared__ float logits_s[NEG_K + 1];
    __shared__ int   cand_s[NEG_K];
    __shared__ __align__(8) unsigned long long mbar_store[RING];

    uint32_t mb[RING];
    #pragma unroll
    for (int s = 0; s < RING; s++) mb[s] = smem_u32(&mbar_store[s]);

    const int sel = __ldg(selection + l);   // uniform, first load

    // Anchor -> registers (needs only sel; overlaps the mask/cand trip below)
    const float4* a4 = (const float4*)(hs + ((size_t)l * S + sel) * H_FIX);
    float4 areg[6];
    #pragma unroll
    for (int i = 0; i < 6; i++) areg[i] = __ldg(a4 + lane + 32 * i);

    if (tid == 64) {
        #pragma unroll
        for (int s = 0; s < RING; s++) mbar_init(mb[s], 1);
    }

    // warp 0: noise + mask-sum -> candidate indices (one parallel trip)
    if (warp == 0) {
        float nz = __ldg(noise + (size_t)l * NEG_K + lane);
        int msum = 0;
        const int* mrow = mask + (size_t)l * S;
        for (int s = lane; s < S; s += 32) msum += mrow[s];
        #pragma unroll
        for (int o = 16; o; o >>= 1) msum += __shfl_xor_sync(0xffffffffu, msum, o);
        const int len_l = msum;
        const bool sir = (sel >= 1) && (sel <= len_l - 1);
        const int n_valid = sir ? (len_l - 2) : (len_l - 1);
        int cand = (int)floorf(nz * (float)n_valid) + 1;
        if (sir && cand >= sel) cand += 1;
        cand_s[lane] = cand;
    }
    __syncthreads();   // cand_s + mbar init visible

    // Prefetch groups 0..2 (18 rows, 54 KB in flight).
    // Stream j = g*GSTREAMS + s. j==0 -> positive row; j>=1 -> negative cand_s[j-1].
    if (tid == 0) {
        mbar_expect_tx(mb[0], GSTREAMS * ROW_BYTES);
        mbar_expect_tx(mb[1], GSTREAMS * ROW_BYTES);
        mbar_expect_tx(mb[2], GSTREAMS * ROW_BYTES);
    }
    if (lane < GSTREAMS && warp < RING) {   // warps 0,1,2 issue groups 0,1,2
        const int g = warp;
        const int j = g * GSTREAMS + lane;
        const float* src = (j == 0)
            ? hs + ((size_t)(valid + l) * S + sel) * H_FIX
            : hs + ((size_t)l * S + cand_s[j - 1]) * H_FIX;
        bulk_cp(smem_u32(&ring[(g * GSTREAMS + lane) * H_FIX]), src, ROW_BYTES, mb[g]);
    }

    // Pipeline: wait slot, compute, refill with group g+3.
    #pragma unroll
    for (int g = 0; g < NGROUPS; g++) {
        const int slot = g % RING;
        mbar_wait(mb[slot], (g >= RING) ? 1 : 0);

        const int j = g * GSTREAMS + warp;
        if (j <= NEG_K) {
            const float4* v4 = (const float4*)&ring[(slot * GSTREAMS + warp) * H_FIX];
            float acc = 0.0f;
            #pragma unroll
            for (int i = 0; i < 6; i++) {
                float4 a = areg[i];
                float4 b = v4[lane + 32 * i];
                acc += a.x*b.x + a.y*b.y + a.z*b.z + a.w*b.w;
            }
            #pragma unroll
            for (int o = 16; o; o >>= 1) acc += __shfl_xor_sync(0xffffffffu, acc, o);
            if (lane == 0) logits_s[j] = acc;
        }
        __syncthreads();   // slot fully consumed by all warps

        const int gn = g + RING;
        if (gn < NGROUPS) {
            const int base = gn * GSTREAMS;
            const int nstr = min(GSTREAMS, NEG_K + 1 - base);   // last group: 3
            if (tid == 0) mbar_expect_tx(mb[slot], (uint32_t)nstr * ROW_BYTES);
            if (tid < nstr) {
                const int j2 = base + tid;   // >= 18, always a negative
                const float* src = hs + ((size_t)l * S + cand_s[j2 - 1]) * H_FIX;
                bulk_cp(smem_u32(&ring[(slot * GSTREAMS + tid) * H_FIX]), src, ROW_BYTES, mb[slot]);
            }
        }
    }

    // Warp 0: parallel logsumexp over 33 logits + grid reduction.
    if (warp == 0) {
        float v = logits_s[lane] * INV_T;
        float e = logits_s[NEG_K] * INV_T;
        float m = (lane == 0) ? fmaxf(v, e) : v;
        #pragma unroll
        for (int o = 16; o; o >>= 1) m = fmaxf(m, __shfl_xor_sync(0xffffffffu, m, o));
        float sse = __expf(v - m);
        if (lane == 0) sse += __expf(e - m);
        #pragma unroll
        for (int o = 16; o; o >>= 1) sse += __shfl_xor_sync(0xffffffffu, sse, o);

        if (lane == 0) {
            float rowloss = (m + logf(sse)) - logits_s[0] * INV_T;
            atomicAdd(&g_sum, rowloss);
            __threadfence();
            int done = atomicAdd(&g_count, 1);
            if (done == loss_size - 1) {
                float total = atomicExch(&g_sum, 0.0f);   // reset for graph replay
                g_count = 0;
                out[0] = (total + (float)valid * logf((float)(NEG_K + 1))) / (float)B;
            }
        }
    }
}

// ---------------- generic fallback (any H), LDG-based ----------------
__global__ __launch_bounds__(256) void infonce_generic_kernel(
    const float* __restrict__ hs, const int* __restrict__ selection,
    const int* __restrict__ mask, const float* __restrict__ noise,
    float* __restrict__ out, int B, int S, int H, int valid, int loss_size)
{
    const int l    = blockIdx.x;
    const int tid  = threadIdx.x;
    const int lane = tid & 31;
    const int warp = tid >> 5;

    __shared__ float logits_s[NEG_K + 1];
    __shared__ int   cand_s[NEG_K];

    const int sel = __ldg(selection + l);
    if (warp == 0) {
        float nz = __ldg(noise + (size_t)l * NEG_K + lane);
        int msum = 0;
        const int* mrow = mask + (size_t)l * S;
        for (int s = lane; s < S; s += 32) msum += mrow[s];
        #pragma unroll
        for (int o = 16; o; o >>= 1) msum += __shfl_xor_sync(0xffffffffu, msum, o);
        const int len_l = msum;
        const bool sir = (sel >= 1) && (sel <= len_l - 1);
        const int n_valid = sir ? (len_l - 2) : (len_l - 1);
        int cand = (int)floorf(nz * (float)n_valid) + 1;
        if (sir && cand >= sel) cand += 1;
        cand_s[lane] = cand;
    }
    __syncthreads();

    const float* a = hs + ((size_t)l * S + sel) * H;
    for (int j = warp; j <= NEG_K; j += blockDim.x >> 5) {
        const float* v = (j == 0)
            ? hs + ((size_t)(valid + l) * S + sel) * H
            : hs + ((size_t)l * S + cand_s[j - 1]) * H;
        float acc = 0.0f;
        for (int i = lane; i < H; i += 32) acc += a[i] * v[i];
        #pragma unroll
        for (int o = 16; o; o >>= 1) acc += __shfl_xor_sync(0xffffffffu, acc, o);
        if (lane == 0) logits_s[j] = acc;
    }
    __syncthreads();

    if (tid == 0) {
        float m = -INFINITY;
        for (int j = 0; j <= NEG_K; j++) m = fmaxf(m, logits_s[j] * INV_T);
        float sse = 0.0f;
        for (int j = 0; j <= NEG_K; j++) sse += __expf(logits_s[j] * INV_T - m);
        float rowloss = (m + logf(sse)) - logits_s[0] * INV_T;
        atomicAdd(&g_sum, rowloss);
        __threadfence();
        int done = atomicAdd(&g_count, 1);
        if (done == loss_size - 1) {
            float total = atomicExch(&g_sum, 0.0f);
            g_count = 0;
            out[0] = (total + (float)valid * logf((float)(NEG_K + 1))) / (float)B;
        }
    }
}

extern "C" void kernel_launch(void* const* d_in, const int* in_sizes, int n_in,
                              void* d_out, int out_size) {
    const float* hs        = (const float*)d_in[0]; // [B,S,H]
    const int*   selection = (const int*)  d_in[1]; // [B]
    const int*   mask      = (const int*)  d_in[2]; // [B,S]
    const float* noise     = (const float*)d_in[3]; // [loss_size, NEG_K]
    float*       out       = (float*)d_out;

    const int B = in_sizes[1];
    const int S = in_sizes[2] / B;
    const int H = in_sizes[0] / (B * S);
    const int loss_size = in_sizes[3] / NEG_K;      // from noise shape (host-side)
    const int valid = B - loss_size;

    if (H == H_FIX) {
        static int smem_set = 0;
        if (!smem_set) {
            cudaFuncSetAttribute(infonce_bulk_kernel,
                                 cudaFuncAttributeMaxDynamicSharedMemorySize, RING_BYTES);
            smem_set = 1;
        }
        infonce_bulk_kernel<<<loss_size, 192, RING_BYTES>>>(hs, selection, mask, noise, out,
                                                            B, S, valid, loss_size);
    } else {
        infonce_generic_kernel<<<loss_size, 256>>>(hs, selection, mask, noise, out,
                                                   B, S, H, valid, loss_size);
    }
}